// round 8
// baseline (speedup 1.0000x reference)
#include <cuda_runtime.h>
#include <cuda_fp16.h>
#include <cstdint>
#include <math.h>

// Problem constants
#define BB   1024
#define LL   2048
#define DEC  64
#define HH   128
#define GG   512         // 4*H gate rows
#define EINF 18          // encoder input features (16 emb + cont*w + x)
#define NKT  10          // k-tiles of 16 (k 0..159; 146..159 zero pad)
#define BT   8           // batch rows per CTA (= mma N)
#define NCTA (BB/BT)     // 128
#define NTHR 256
#define XST  200         // xhT row stride in fp16 (conflict-free B-frag banks)
#define NFRAG 10240      // 8 warps * 4 mtiles * 10 ktiles * 32 lanes

// ---------------- persistent device scratch ----------------
__device__ uint4 g_Whf_e[NFRAG];   // enc W fp16, mma-fragment order (rows permuted)
__device__ uint4 g_Whf_d[NFRAG];   // dec
__device__ float g_fe[(size_t)BB * LL * EINF];
__device__ float g_fd[BB * DEC * 17];

// ---------------- smem byte layout ----------------
#define XH0_OFF   0                         // 3200 B : xh^T fp16 [8][200] buf 0
#define XH1_OFF   3200                      // 3200 B : buf 1
#define HBUF_OFF  6400                      // 4096 B : h fp32 [128][8] (decoder)
#define HW_OFF    10496                     // 3096 B : head weights/biases
#define SMEM_TOTAL 13592

// ---------------- mma wrapper ----------------
__device__ __forceinline__ void mma_f16(float* d, const uint4& a,
                                        uint32_t b0, uint32_t b1) {
    asm volatile(
        "mma.sync.aligned.m16n8k16.row.col.f32.f16.f16.f32 "
        "{%0,%1,%2,%3}, {%4,%5,%6,%7}, {%8,%9}, {%0,%1,%2,%3};"
        : "+f"(d[0]), "+f"(d[1]), "+f"(d[2]), "+f"(d[3])
        : "r"(a.x), "r"(a.y), "r"(a.z), "r"(a.w), "r"(b0), "r"(b1));
}

// ---------------- fast activations (HW tanh) ----------------
__device__ __forceinline__ float th(float x) {
    float y;
    asm("tanh.approx.f32 %0, %1;" : "=f"(y) : "f"(x));
    return y;
}
__device__ __forceinline__ float sg(float x) {
    return fmaf(0.5f, th(0.5f * x), 0.5f);
}

// ---------------- prep kernels ----------------
__device__ __forceinline__ float getW(const float* Wih, const float* Whh,
                                      int R, int k) {
    if (k < 18)  return Wih[R * 18 + k];
    if (k < 146) return Whh[R * 128 + (k - 18)];
    return 0.0f;
}
__device__ __forceinline__ uint32_t packh2(float a, float b) {
    __half2 h = __floats2half2_rn(a, b);   // low = a
    return *reinterpret_cast<uint32_t*>(&h);
}

// Row permutation: mma-space row (w, mt, g, s) -> gate row mt*128 + w*16 + 2g + s.
// Result: thread (w,lane)'s 16 accumulators = gates {i,f,g,o} x elems {j0,j0+1}
// x cols {2t4, 2t4+1}, so the LSTM cell runs entirely in registers.
__global__ void prep_Wfrag(const float* __restrict__ Wih,
                           const float* __restrict__ Whh,
                           uint4* __restrict__ w_out) {
    int idx = blockIdx.x * blockDim.x + threadIdx.x;
    if (idx >= NFRAG) return;
    int frag = idx >> 5, lane = idx & 31;
    int w = frag / 40, rem = frag - w * 40;
    int mt = rem / 10, kt = rem - mt * 10;
    int g = lane >> 2, t4 = lane & 3;
    int R0 = mt * 128 + w * 16 + 2 * g;   // s=0 (mma row g)
    int R1 = R0 + 1;                      // s=1 (mma row g+8)
    int kc = kt * 16 + 2 * t4;
    float v[8];
    v[0] = getW(Wih, Whh, R0, kc);     v[1] = getW(Wih, Whh, R0, kc + 1);
    v[2] = getW(Wih, Whh, R1, kc);     v[3] = getW(Wih, Whh, R1, kc + 1);
    v[4] = getW(Wih, Whh, R0, kc + 8); v[5] = getW(Wih, Whh, R0, kc + 9);
    v[6] = getW(Wih, Whh, R1, kc + 8); v[7] = getW(Wih, Whh, R1, kc + 9);
    w_out[idx] = make_uint4(packh2(v[0], v[1]), packh2(v[2], v[3]),
                            packh2(v[4], v[5]), packh2(v[6], v[7]));
}

__global__ void prep_fe(const int* __restrict__ cat, const float* __restrict__ cont,
                        const float* __restrict__ X, const float* __restrict__ emb,
                        const float* __restrict__ cw, float* __restrict__ out) {
    size_t idx = (size_t)blockIdx.x * blockDim.x + threadIdx.x;
    if (idx >= (size_t)BB * LL * EINF) return;
    size_t bl = idx / EINF;
    int j = (int)(idx - bl * EINF);
    float v;
    if (j < 16)       v = emb[cat[bl] * 16 + j];
    else if (j == 16) v = cont[bl] * cw[0];
    else              v = X[bl];
    out[idx] = v;
}

__global__ void prep_fd(const int* __restrict__ cat, const float* __restrict__ cont,
                        const float* __restrict__ emb, const float* __restrict__ cw,
                        float* __restrict__ out) {
    int idx = blockIdx.x * blockDim.x + threadIdx.x;
    if (idx >= BB * DEC * 17) return;
    int bl = idx / 17, j = idx - bl * 17;
    out[idx] = (j < 16) ? emb[cat[bl] * 16 + j] : cont[bl] * cw[0];
}

// ---------------- main persistent kernel ----------------
__global__ void __launch_bounds__(NTHR, 1)
model_kernel(const float* __restrict__ b_e, const float* __restrict__ b_d,
             const float* __restrict__ Wm, const float* __restrict__ bm,
             const float* __restrict__ Wsw, const float* __restrict__ bs,
             const float* __restrict__ Wv, const float* __restrict__ bv,
             float* __restrict__ out) {
    extern __shared__ char smem[];
    __half* xbuf[2] = { reinterpret_cast<__half*>(smem + XH0_OFF),
                        reinterpret_cast<__half*>(smem + XH1_OFF) };
    float*  hbuf = reinterpret_cast<float*>(smem + HBUF_OFF);
    float*  hw   = reinterpret_cast<float*>(smem + HW_OFF);

    const int tid = threadIdx.x;
    const int b0r = blockIdx.x * BT;
    const int w = tid >> 5, lane = tid & 31;
    const int g = lane >> 2, t4 = lane & 3;
    const int j0 = w * 16 + 2 * g;        // this thread's 2 cell elems: j0, j0+1
    const int c0 = 2 * t4;                // this thread's 2 batch cols: c0, c0+1
    const int wrp = w;

    // ---- load encoder W into registers (fragment order) ----
    uint4 Wh[40];
    {
        const uint4* src = g_Whf_e + (size_t)w * 40 * 32 + lane;
#pragma unroll
        for (int i = 0; i < 40; ++i) Wh[i] = src[i * 32];
    }
    // biases: bA -> elem j0 (d slots 0,1), bB -> elem j0+1 (slots 2,3)
    float bA[4], bB[4];
#pragma unroll
    for (int mt = 0; mt < 4; ++mt) {
        bA[mt] = b_e[mt * 128 + j0];
        bB[mt] = b_e[mt * 128 + j0 + 1];
    }

    // zero both xh buffers (h0 = 0; K padding stays 0 forever)
    for (int i = tid; i < (2 * BT * XST) / 2; i += NTHR)
        reinterpret_cast<uint32_t*>(xbuf[0])[i] = 0;

    // head weights
    if (tid < 128) {
        hw[tid]       = Wm[tid];
        hw[128 + tid] = Wsw[tid];
#pragma unroll
        for (int d = 0; d < 4; ++d) hw[256 + d * 128 + tid] = Wv[d * 128 + tid];
    }
    if (tid == 0) {
        hw[768] = bm[0]; hw[769] = bs[0];
        hw[770] = bv[0]; hw[771] = bv[1]; hw[772] = bv[2]; hw[773] = bv[3];
    }
    __syncthreads();
    // initial x features (t=0) -> buffer 0
    if (tid < BT * EINF) {
        int pr = tid / EINF, pk = tid - pr * EINF;
        xbuf[0][pr * XST + pk] =
            __float2half(g_fe[(size_t)(b0r + pr) * (LL * EINF) + pk]);
    }

    float c[4] = {0.f, 0.f, 0.f, 0.f};   // states: (j0,c0),(j0,c1),(j1,c0),(j1,c1)

#pragma unroll 1
    for (int t = 0; t < LL + DEC; ++t) {
        if (t == LL) {
            const uint4* src = g_Whf_d + (size_t)w * 40 * 32 + lane;
#pragma unroll
            for (int i = 0; i < 40; ++i) Wh[i] = src[i * 32];
#pragma unroll
            for (int mt = 0; mt < 4; ++mt) {
                bA[mt] = b_d[mt * 128 + j0];
                bB[mt] = b_d[mt * 128 + j0 + 1];
            }
        }
        const __half* cur = xbuf[t & 1];
        __half*       nxt = xbuf[(t + 1) & 1];
        __syncthreads();                      // cur complete (h + features)

        // ---- load B fragments (conflict-free banks with XST=200) ----
        const __half* xp = cur + g * XST;
        uint32_t Bf0[NKT], Bf1[NKT];
#pragma unroll
        for (int kt = 0; kt < NKT; ++kt) {
            Bf0[kt] = *reinterpret_cast<const uint32_t*>(xp + kt * 16 + 2 * t4);
            Bf1[kt] = *reinterpret_cast<const uint32_t*>(xp + kt * 16 + 2 * t4 + 8);
        }

        // ---- gate GEMM: mt 0..3 = i,f,g,o rows for elems j0,j0+1 ----
        float di[4], df[4], dg[4], dd[4];
        di[0] = bA[0]; di[1] = bA[0]; di[2] = bB[0]; di[3] = bB[0];
        df[0] = bA[1]; df[1] = bA[1]; df[2] = bB[1]; df[3] = bB[1];
        dg[0] = bA[2]; dg[1] = bA[2]; dg[2] = bB[2]; dg[3] = bB[2];
        dd[0] = bA[3]; dd[1] = bA[3]; dd[2] = bB[3]; dd[3] = bB[3];
#pragma unroll
        for (int kt = 0; kt < NKT; ++kt) {
            mma_f16(di, Wh[0 * 10 + kt], Bf0[kt], Bf1[kt]);
            mma_f16(df, Wh[1 * 10 + kt], Bf0[kt], Bf1[kt]);
            mma_f16(dg, Wh[2 * 10 + kt], Bf0[kt], Bf1[kt]);
            mma_f16(dd, Wh[3 * 10 + kt], Bf0[kt], Bf1[kt]);
        }

        // ---- LSTM cell: fully in registers ----
        float h[4];
#pragma unroll
        for (int q = 0; q < 4; ++q) {
            c[q] = sg(df[q]) * c[q] + sg(di[q]) * th(dg[q]);
            h[q] = sg(dd[q]) * th(c[q]);
        }
        // h -> next buffer: slots (q0,q2) = col c0 elems j0,j0+1 ; (q1,q3) = col c0+1
        *reinterpret_cast<uint32_t*>(nxt + c0 * XST + 18 + j0)       = packh2(h[0], h[2]);
        *reinterpret_cast<uint32_t*>(nxt + (c0 + 1) * XST + 18 + j0) = packh2(h[1], h[3]);

        // ---- features for next step -> next buffer ----
        if (t < LL - 1) {
            if (tid < BT * EINF) {
                int pr = tid / EINF, pk = tid - pr * EINF;
                nxt[pr * XST + pk] = __float2half(
                    g_fe[(size_t)(b0r + pr) * (LL * EINF) + (size_t)(t + 1) * EINF + pk]);
            }
        } else if (t == LL - 1) {
            // decoder t0 reuses encoder's last features (f_prev, x_prev)
            if (tid < BT * EINF) {
                int pr = tid / EINF, pk = tid - pr * EINF;
                nxt[pr * XST + pk] = cur[pr * XST + pk];
            }
        } else if (t < LL + DEC - 1) {
            int td = t - LL;
            if (tid < BT * 17) {
                int pr = tid / 17, pk = tid - pr * 17;
                nxt[pr * XST + pk] =
                    __float2half(g_fd[((b0r + pr) * DEC + td) * 17 + pk]);
            }
        }

        // ---- decoder heads ----
        if (t >= LL) {
            int td = t - LL;
            *reinterpret_cast<float2*>(hbuf + j0 * BT + c0)       = make_float2(h[0], h[1]);
            *reinterpret_cast<float2*>(hbuf + (j0 + 1) * BT + c0) = make_float2(h[2], h[3]);
            __syncthreads();                  // h complete for heads
            int r = wrp;                      // 8 warps -> 8 batch rows
            float hm = 0.f, hs = 0.f, hv0 = 0.f, hv1 = 0.f, hv2 = 0.f, hv3 = 0.f;
#pragma unroll
            for (int q4 = 0; q4 < 4; ++q4) {
                int jj = lane + q4 * 32;
                float hh = hbuf[jj * BT + r];
                hm  = fmaf(hh, hw[jj], hm);
                hs  = fmaf(hh, hw[128 + jj], hs);
                hv0 = fmaf(hh, hw[256 + jj], hv0);
                hv1 = fmaf(hh, hw[384 + jj], hv1);
                hv2 = fmaf(hh, hw[512 + jj], hv2);
                hv3 = fmaf(hh, hw[640 + jj], hv3);
            }
#pragma unroll
            for (int off = 16; off; off >>= 1) {
                hm  += __shfl_xor_sync(0xffffffffu, hm,  off);
                hs  += __shfl_xor_sync(0xffffffffu, hs,  off);
                hv0 += __shfl_xor_sync(0xffffffffu, hv0, off);
                hv1 += __shfl_xor_sync(0xffffffffu, hv1, off);
                hv2 += __shfl_xor_sync(0xffffffffu, hv2, off);
                hv3 += __shfl_xor_sync(0xffffffffu, hv3, off);
            }
            if (lane == 0) {
                float mu = hm + hw[768];
                float sp = hs + hw[769];
                float stdv = fmaxf(sp, 0.0f) + log1pf(__expf(-fabsf(sp)));
                int b = b0r + r;
                out[b * DEC + td] = mu;
                out[BB * DEC + b * DEC + td] = stdv;
                float* vo = out + 2 * BB * DEC + (b * DEC + td) * 4;
                vo[0] = hv0 + hw[770]; vo[1] = hv1 + hw[771];
                vo[2] = hv2 + hw[772]; vo[3] = hv3 + hw[773];
                nxt[r * XST + 17] = __float2half(mu);   // mu feedback -> x_prev
            }
        }
    }
}

// ---------------- launch ----------------
extern "C" void kernel_launch(void* const* d_in, const int* in_sizes, int n_in,
                              void* d_out, int out_size) {
    const int*   cat_in   = (const int*)d_in[0];
    const float* cont_in  = (const float*)d_in[1];
    const float* X_in     = (const float*)d_in[2];
    const int*   cat_out  = (const int*)d_in[3];
    const float* cont_out = (const float*)d_in[4];
    const float* emb      = (const float*)d_in[5];
    const float* cw       = (const float*)d_in[6];
    const float* Wih_e    = (const float*)d_in[7];
    const float* Whh_e    = (const float*)d_in[8];
    const float* b_e      = (const float*)d_in[9];
    const float* Wih_d    = (const float*)d_in[10];
    const float* Whh_d    = (const float*)d_in[11];
    const float* b_d      = (const float*)d_in[12];
    const float* Wm       = (const float*)d_in[13];
    const float* bm       = (const float*)d_in[14];
    const float* Ws       = (const float*)d_in[15];
    const float* bs       = (const float*)d_in[16];
    const float* Wv       = (const float*)d_in[17];
    const float* bv       = (const float*)d_in[18];
    float* out = (float*)d_out;

    uint4 *pWhe, *pWhd;
    float *pfe, *pfd;
    cudaGetSymbolAddress((void**)&pWhe, g_Whf_e);
    cudaGetSymbolAddress((void**)&pWhd, g_Whf_d);
    cudaGetSymbolAddress((void**)&pfe,  g_fe);
    cudaGetSymbolAddress((void**)&pfd,  g_fd);

    prep_Wfrag<<<(NFRAG + 255) / 256, 256>>>(Wih_e, Whh_e, pWhe);
    prep_Wfrag<<<(NFRAG + 255) / 256, 256>>>(Wih_d, Whh_d, pWhd);
    size_t ne = (size_t)BB * LL * EINF;
    prep_fe<<<(unsigned)((ne + 255) / 256), 256>>>(cat_in, cont_in, X_in, emb, cw, pfe);
    prep_fd<<<(BB * DEC * 17 + 255) / 256, 256>>>(cat_out, cont_out, emb, cw, pfd);

    cudaFuncSetAttribute(model_kernel, cudaFuncAttributeMaxDynamicSharedMemorySize,
                         SMEM_TOTAL);
    model_kernel<<<NCTA, NTHR, SMEM_TOTAL>>>(b_e, b_d, Wm, bm, Ws, bs, Wv, bv, out);
}

// round 10
// speedup vs baseline: 1.0809x; 1.0809x over previous
#include <cuda_runtime.h>
#include <cuda_fp16.h>
#include <cstdint>
#include <math.h>

// Problem constants
#define BB   1024
#define LL   2048
#define DEC  64
#define HH   128
#define GG   512         // 4*H gate rows
#define EINF 18          // encoder input features (16 emb + cont*w + x)
#define NKT  10          // k-tiles of 16 (k 0..159; 146..159 zero pad)
#define BT   8           // batch rows per CTA (= mma N)
#define NCTA (BB/BT)     // 128
#define NTHR 256
#define XST  200         // xhT row stride in fp16 (conflict-free B-frag banks)
#define NFRAG 10240      // 8 warps * 4 mtiles * 10 ktiles * 32 lanes

// ---------------- persistent device scratch ----------------
__device__ uint4 g_Whf_e[NFRAG];   // enc W fp16, mma-fragment order (rows permuted)
__device__ uint4 g_Whf_d[NFRAG];   // dec
__device__ float g_fe[(size_t)BB * LL * EINF];
__device__ float g_fd[BB * DEC * 17];

// ---------------- smem byte layout ----------------
#define XH0_OFF   0                         // 3200 B : xh^T fp16 [8][200] buf 0
#define XH1_OFF   3200                      // 3200 B : buf 1
#define HBUF_OFF  6400                      // 4096 B : h fp32 [128][8] (decoder)
#define HW_OFF    10496                     // 3096 B : head weights/biases
#define SMEM_TOTAL 13592

// ---------------- mma wrapper ----------------
__device__ __forceinline__ void mma_f16(float* d, const uint4& a,
                                        uint32_t b0, uint32_t b1) {
    asm volatile(
        "mma.sync.aligned.m16n8k16.row.col.f32.f16.f16.f32 "
        "{%0,%1,%2,%3}, {%4,%5,%6,%7}, {%8,%9}, {%0,%1,%2,%3};"
        : "+f"(d[0]), "+f"(d[1]), "+f"(d[2]), "+f"(d[3])
        : "r"(a.x), "r"(a.y), "r"(a.z), "r"(a.w), "r"(b0), "r"(b1));
}

// ---------------- fast activations (HW tanh) ----------------
__device__ __forceinline__ float th(float x) {
    float y;
    asm("tanh.approx.f32 %0, %1;" : "=f"(y) : "f"(x));
    return y;
}
__device__ __forceinline__ float sg(float x) {
    return fmaf(0.5f, th(0.5f * x), 0.5f);
}

// ---------------- prep kernels ----------------
__device__ __forceinline__ float getW(const float* Wih, const float* Whh,
                                      int R, int k) {
    if (k < 18)  return Wih[R * 18 + k];
    if (k < 146) return Whh[R * 128 + (k - 18)];
    return 0.0f;
}
__device__ __forceinline__ uint32_t packh2(float a, float b) {
    __half2 h = __floats2half2_rn(a, b);   // low = a
    return *reinterpret_cast<uint32_t*>(&h);
}

// Row permutation: mma-space row (w, mt, g, s) -> gate row mt*128 + w*16 + 2g + s.
// Thread (w,lane)'s accumulators = gates {i,f,g,o} x elems {j0,j0+1} x cols {c0,c0+1}.
__global__ void prep_Wfrag(const float* __restrict__ Wih,
                           const float* __restrict__ Whh,
                           uint4* __restrict__ w_out) {
    int idx = blockIdx.x * blockDim.x + threadIdx.x;
    if (idx >= NFRAG) return;
    int frag = idx >> 5, lane = idx & 31;
    int w = frag / 40, rem = frag - w * 40;
    int mt = rem / 10, kt = rem - mt * 10;
    int g = lane >> 2, t4 = lane & 3;
    int R0 = mt * 128 + w * 16 + 2 * g;   // s=0 (mma row g)
    int R1 = R0 + 1;                      // s=1 (mma row g+8)
    int kc = kt * 16 + 2 * t4;
    float v[8];
    v[0] = getW(Wih, Whh, R0, kc);     v[1] = getW(Wih, Whh, R0, kc + 1);
    v[2] = getW(Wih, Whh, R1, kc);     v[3] = getW(Wih, Whh, R1, kc + 1);
    v[4] = getW(Wih, Whh, R0, kc + 8); v[5] = getW(Wih, Whh, R0, kc + 9);
    v[6] = getW(Wih, Whh, R1, kc + 8); v[7] = getW(Wih, Whh, R1, kc + 9);
    w_out[idx] = make_uint4(packh2(v[0], v[1]), packh2(v[2], v[3]),
                            packh2(v[4], v[5]), packh2(v[6], v[7]));
}

__global__ void prep_fe(const int* __restrict__ cat, const float* __restrict__ cont,
                        const float* __restrict__ X, const float* __restrict__ emb,
                        const float* __restrict__ cw, float* __restrict__ out) {
    size_t idx = (size_t)blockIdx.x * blockDim.x + threadIdx.x;
    if (idx >= (size_t)BB * LL * EINF) return;
    size_t bl = idx / EINF;
    int j = (int)(idx - bl * EINF);
    float v;
    if (j < 16)       v = emb[cat[bl] * 16 + j];
    else if (j == 16) v = cont[bl] * cw[0];
    else              v = X[bl];
    out[idx] = v;
}

__global__ void prep_fd(const int* __restrict__ cat, const float* __restrict__ cont,
                        const float* __restrict__ emb, const float* __restrict__ cw,
                        float* __restrict__ out) {
    int idx = blockIdx.x * blockDim.x + threadIdx.x;
    if (idx >= BB * DEC * 17) return;
    int bl = idx / 17, j = idx - bl * 17;
    out[idx] = (j < 16) ? emb[cat[bl] * 16 + j] : cont[bl] * cw[0];
}

// ---------------- main persistent kernel ----------------
__global__ void __launch_bounds__(NTHR, 1)
model_kernel(const float* __restrict__ b_e, const float* __restrict__ b_d,
             const float* __restrict__ Wm, const float* __restrict__ bm,
             const float* __restrict__ Wsw, const float* __restrict__ bs,
             const float* __restrict__ Wv, const float* __restrict__ bv,
             float* __restrict__ out) {
    extern __shared__ char smem[];
    __half* xbuf[2] = { reinterpret_cast<__half*>(smem + XH0_OFF),
                        reinterpret_cast<__half*>(smem + XH1_OFF) };
    float*  hbuf = reinterpret_cast<float*>(smem + HBUF_OFF);
    float*  hw   = reinterpret_cast<float*>(smem + HW_OFF);

    const int tid = threadIdx.x;
    const int b0r = blockIdx.x * BT;
    const int w = tid >> 5, lane = tid & 31;
    const int g = lane >> 2, t4 = lane & 3;
    const int j0 = w * 16 + 2 * g;        // this thread's 2 cell elems: j0, j0+1
    const int c0 = 2 * t4;                // this thread's 2 batch cols: c0, c0+1

    // ---- load encoder W into registers (fragment order) ----
    uint4 Wh[40];
    {
        const uint4* src = g_Whf_e + (size_t)w * 40 * 32 + lane;
#pragma unroll
        for (int i = 0; i < 40; ++i) Wh[i] = src[i * 32];
    }
    // biases: bA -> elem j0 (d slots 0,1), bB -> elem j0+1 (slots 2,3)
    float bA[4], bB[4];
#pragma unroll
    for (int mt = 0; mt < 4; ++mt) {
        bA[mt] = b_e[mt * 128 + j0];
        bB[mt] = b_e[mt * 128 + j0 + 1];
    }

    // zero both xh buffers (h0 = 0; K padding stays 0 forever)
    for (int i = tid; i < (2 * BT * XST) / 2; i += NTHR)
        reinterpret_cast<uint32_t*>(xbuf[0])[i] = 0;

    // head weights
    if (tid < 128) {
        hw[tid]       = Wm[tid];
        hw[128 + tid] = Wsw[tid];
#pragma unroll
        for (int d = 0; d < 4; ++d) hw[256 + d * 128 + tid] = Wv[d * 128 + tid];
    }
    if (tid == 0) {
        hw[768] = bm[0]; hw[769] = bs[0];
        hw[770] = bv[0]; hw[771] = bv[1]; hw[772] = bv[2]; hw[773] = bv[3];
    }
    __syncthreads();
    // initial x features (t=0) -> buffer 0
    if (tid < BT * EINF) {
        int pr = tid / EINF, pk = tid - pr * EINF;
        xbuf[0][pr * XST + pk] =
            __float2half(g_fe[(size_t)(b0r + pr) * (LL * EINF) + pk]);
    }

    float c[4] = {0.f, 0.f, 0.f, 0.f};   // states: (j0,c0),(j0,c1),(j1,c0),(j1,c1)

#pragma unroll 1
    for (int t = 0; t < LL + DEC; ++t) {
        if (t == LL) {
            const uint4* src = g_Whf_d + (size_t)w * 40 * 32 + lane;
#pragma unroll
            for (int i = 0; i < 40; ++i) Wh[i] = src[i * 32];
#pragma unroll
            for (int mt = 0; mt < 4; ++mt) {
                bA[mt] = b_d[mt * 128 + j0];
                bB[mt] = b_d[mt * 128 + j0 + 1];
            }
        }
        const __half* cur = xbuf[t & 1];
        __half*       nxt = xbuf[(t + 1) & 1];
        __syncthreads();                      // cur complete (h + features)

        // ---- load B fragments (conflict-free banks with XST=200) ----
        const __half* xp = cur + g * XST;
        uint32_t Bf0[NKT], Bf1[NKT];
#pragma unroll
        for (int kt = 0; kt < NKT; ++kt) {
            Bf0[kt] = *reinterpret_cast<const uint32_t*>(xp + kt * 16 + 2 * t4);
            Bf1[kt] = *reinterpret_cast<const uint32_t*>(xp + kt * 16 + 2 * t4 + 8);
        }

        // ---- ISSUE feature prefetch LDG now; MMA phase hides its latency ----
        float pf = 0.0f; bool havepf = false; int pr = 0, pk = 0;
        if (t < LL - 1) {
            if (tid < BT * EINF) {
                havepf = true; pr = tid / EINF; pk = tid - pr * EINF;
                pf = g_fe[(size_t)(b0r + pr) * (LL * EINF) + (size_t)(t + 1) * EINF + pk];
            }
        } else if (t >= LL && t < LL + DEC - 1) {
            int td = t - LL;
            if (tid < BT * 17) {
                havepf = true; pr = tid / 17; pk = tid - pr * 17;
                pf = g_fd[((b0r + pr) * DEC + td) * 17 + pk];
            }
        }

        // ---- gate GEMM: 8 independent 5-deep K-chains (halved dep latency) ----
        float di[4], df[4], dg[4], dd[4];      // k-tiles 0..4
        float ei[4], ef[4], eg[4], ed[4];      // k-tiles 5..9
        di[0] = bA[0]; di[1] = bA[0]; di[2] = bB[0]; di[3] = bB[0];
        df[0] = bA[1]; df[1] = bA[1]; df[2] = bB[1]; df[3] = bB[1];
        dg[0] = bA[2]; dg[1] = bA[2]; dg[2] = bB[2]; dg[3] = bB[2];
        dd[0] = bA[3]; dd[1] = bA[3]; dd[2] = bB[3]; dd[3] = bB[3];
#pragma unroll
        for (int q = 0; q < 4; ++q) { ei[q] = 0.f; ef[q] = 0.f; eg[q] = 0.f; ed[q] = 0.f; }
#pragma unroll
        for (int kt = 0; kt < 5; ++kt) {
            mma_f16(di, Wh[0 * 10 + kt], Bf0[kt], Bf1[kt]);
            mma_f16(df, Wh[1 * 10 + kt], Bf0[kt], Bf1[kt]);
            mma_f16(dg, Wh[2 * 10 + kt], Bf0[kt], Bf1[kt]);
            mma_f16(dd, Wh[3 * 10 + kt], Bf0[kt], Bf1[kt]);
            mma_f16(ei, Wh[0 * 10 + kt + 5], Bf0[kt + 5], Bf1[kt + 5]);
            mma_f16(ef, Wh[1 * 10 + kt + 5], Bf0[kt + 5], Bf1[kt + 5]);
            mma_f16(eg, Wh[2 * 10 + kt + 5], Bf0[kt + 5], Bf1[kt + 5]);
            mma_f16(ed, Wh[3 * 10 + kt + 5], Bf0[kt + 5], Bf1[kt + 5]);
        }

        // ---- LSTM cell: fully in registers ----
        float h[4];
#pragma unroll
        for (int q = 0; q < 4; ++q) {
            float gi = di[q] + ei[q];
            float gf = df[q] + ef[q];
            float gc = dg[q] + eg[q];
            float go = dd[q] + ed[q];
            c[q] = sg(gf) * c[q] + sg(gi) * th(gc);
            h[q] = sg(go) * th(c[q]);
        }
        // h -> next buffer (conflict-free permutation banks)
        *reinterpret_cast<uint32_t*>(nxt + c0 * XST + 18 + j0)       = packh2(h[0], h[2]);
        *reinterpret_cast<uint32_t*>(nxt + (c0 + 1) * XST + 18 + j0) = packh2(h[1], h[3]);

        // ---- store prefetched features / seam copy ----
        if (havepf) {
            nxt[pr * XST + pk] = __float2half(pf);
        } else if (t == LL - 1) {
            // decoder t0 reuses encoder's last features (f_prev, x_prev)
            if (tid < BT * EINF) {
                int qr = tid / EINF, qk = tid - qr * EINF;
                nxt[qr * XST + qk] = cur[qr * XST + qk];
            }
        }

        // ---- decoder heads ----
        if (t >= LL) {
            int td = t - LL;
            *reinterpret_cast<float2*>(hbuf + j0 * BT + c0)       = make_float2(h[0], h[1]);
            *reinterpret_cast<float2*>(hbuf + (j0 + 1) * BT + c0) = make_float2(h[2], h[3]);
            __syncthreads();                  // h complete for heads
            int r = w;                        // 8 warps -> 8 batch rows
            float hm = 0.f, hs = 0.f, hv0 = 0.f, hv1 = 0.f, hv2 = 0.f, hv3 = 0.f;
#pragma unroll
            for (int q4 = 0; q4 < 4; ++q4) {
                int jj = lane + q4 * 32;
                float hh = hbuf[jj * BT + r];
                hm  = fmaf(hh, hw[jj], hm);
                hs  = fmaf(hh, hw[128 + jj], hs);
                hv0 = fmaf(hh, hw[256 + jj], hv0);
                hv1 = fmaf(hh, hw[384 + jj], hv1);
                hv2 = fmaf(hh, hw[512 + jj], hv2);
                hv3 = fmaf(hh, hw[640 + jj], hv3);
            }
#pragma unroll
            for (int off = 16; off; off >>= 1) {
                hm  += __shfl_xor_sync(0xffffffffu, hm,  off);
                hs  += __shfl_xor_sync(0xffffffffu, hs,  off);
                hv0 += __shfl_xor_sync(0xffffffffu, hv0, off);
                hv1 += __shfl_xor_sync(0xffffffffu, hv1, off);
                hv2 += __shfl_xor_sync(0xffffffffu, hv2, off);
                hv3 += __shfl_xor_sync(0xffffffffu, hv3, off);
            }
            if (lane == 0) {
                float mu = hm + hw[768];
                float sp = hs + hw[769];
                float stdv = fmaxf(sp, 0.0f) + log1pf(__expf(-fabsf(sp)));
                int b = b0r + r;
                out[b * DEC + td] = mu;
                out[BB * DEC + b * DEC + td] = stdv;
                float* vo = out + 2 * BB * DEC + (b * DEC + td) * 4;
                vo[0] = hv0 + hw[770]; vo[1] = hv1 + hw[771];
                vo[2] = hv2 + hw[772]; vo[3] = hv3 + hw[773];
                nxt[r * XST + 17] = __float2half(mu);   // mu feedback -> x_prev
            }
        }
    }
}

// ---------------- launch ----------------
extern "C" void kernel_launch(void* const* d_in, const int* in_sizes, int n_in,
                              void* d_out, int out_size) {
    const int*   cat_in   = (const int*)d_in[0];
    const float* cont_in  = (const float*)d_in[1];
    const float* X_in     = (const float*)d_in[2];
    const int*   cat_out  = (const int*)d_in[3];
    const float* cont_out = (const float*)d_in[4];
    const float* emb      = (const float*)d_in[5];
    const float* cw       = (const float*)d_in[6];
    const float* Wih_e    = (const float*)d_in[7];
    const float* Whh_e    = (const float*)d_in[8];
    const float* b_e      = (const float*)d_in[9];
    const float* Wih_d    = (const float*)d_in[10];
    const float* Whh_d    = (const float*)d_in[11];
    const float* b_d      = (const float*)d_in[12];
    const float* Wm       = (const float*)d_in[13];
    const float* bm       = (const float*)d_in[14];
    const float* Ws       = (const float*)d_in[15];
    const float* bs       = (const float*)d_in[16];
    const float* Wv       = (const float*)d_in[17];
    const float* bv       = (const float*)d_in[18];
    float* out = (float*)d_out;

    uint4 *pWhe, *pWhd;
    float *pfe, *pfd;
    cudaGetSymbolAddress((void**)&pWhe, g_Whf_e);
    cudaGetSymbolAddress((void**)&pWhd, g_Whf_d);
    cudaGetSymbolAddress((void**)&pfe,  g_fe);
    cudaGetSymbolAddress((void**)&pfd,  g_fd);

    prep_Wfrag<<<(NFRAG + 255) / 256, 256>>>(Wih_e, Whh_e, pWhe);
    prep_Wfrag<<<(NFRAG + 255) / 256, 256>>>(Wih_d, Whh_d, pWhd);
    size_t ne = (size_t)BB * LL * EINF;
    prep_fe<<<(unsigned)((ne + 255) / 256), 256>>>(cat_in, cont_in, X_in, emb, cw, pfe);
    prep_fd<<<(BB * DEC * 17 + 255) / 256, 256>>>(cat_out, cont_out, emb, cw, pfd);

    cudaFuncSetAttribute(model_kernel, cudaFuncAttributeMaxDynamicSharedMemorySize,
                         SMEM_TOTAL);
    model_kernel<<<NCTA, NTHR, SMEM_TOTAL>>>(b_e, b_d, Wm, bm, Ws, bs, Wv, bv, out);
}

// round 11
// speedup vs baseline: 1.2930x; 1.1962x over previous
#include <cuda_runtime.h>
#include <cuda_fp16.h>
#include <cstdint>
#include <math.h>

// Problem constants
#define BB   1024
#define LL   2048
#define DEC  64
#define HH   128
#define GG   512         // 4*H gate rows
#define EINF 18          // encoder input features (16 emb + cont*w + x)
#define NKT  10          // k-tiles of 16 (k 0..159; 146..159 zero pad)
#define BT   8           // batch rows per CTA (= mma N)
#define NCTA (BB/BT)     // 128
#define NTHR 512         // 16 warps -> 4 per SMSP (latency hiding)
#define NW   16
#define XST  200         // xhT row stride in fp16 (conflict-free B-frag banks)
#define FPW  20          // W fragments per warp: 2 mtiles x 10 ktiles
#define NFRAG (NW * FPW * 32)   // 10240

// ---------------- persistent device scratch ----------------
__device__ uint4 g_Whf_e[NFRAG];   // enc W fp16, mma-fragment order (rows permuted)
__device__ uint4 g_Whf_d[NFRAG];   // dec
__device__ float g_fe[(size_t)BB * LL * EINF];
__device__ float g_fd[BB * DEC * 17];

// ---------------- smem byte layout ----------------
#define XH0_OFF   0                         // 3200 B : xh^T fp16 [8][200] buf 0
#define XH1_OFF   3200                      // 3200 B : buf 1
#define HBUF_OFF  6400                      // 4096 B : h fp32 [128][8] (decoder)
#define HW_OFF    10496                     // 3096 B : head weights/biases
#define SMEM_TOTAL 13592

// ---------------- mma wrapper ----------------
__device__ __forceinline__ void mma_f16(float* d, const uint4& a,
                                        uint32_t b0, uint32_t b1) {
    asm volatile(
        "mma.sync.aligned.m16n8k16.row.col.f32.f16.f16.f32 "
        "{%0,%1,%2,%3}, {%4,%5,%6,%7}, {%8,%9}, {%0,%1,%2,%3};"
        : "+f"(d[0]), "+f"(d[1]), "+f"(d[2]), "+f"(d[3])
        : "r"(a.x), "r"(a.y), "r"(a.z), "r"(a.w), "r"(b0), "r"(b1));
}

// ---------------- fast activations (HW tanh) ----------------
__device__ __forceinline__ float th(float x) {
    float y;
    asm("tanh.approx.f32 %0, %1;" : "=f"(y) : "f"(x));
    return y;
}
__device__ __forceinline__ float sg(float x) {
    return fmaf(0.5f, th(0.5f * x), 0.5f);
}

// ---------------- prep kernels ----------------
__device__ __forceinline__ float getW(const float* Wih, const float* Whh,
                                      int R, int k) {
    if (k < 18)  return Wih[R * 18 + k];
    if (k < 146) return Whh[R * 128 + (k - 18)];
    return 0.0f;
}
__device__ __forceinline__ uint32_t packh2(float a, float b) {
    __half2 h = __floats2half2_rn(a, b);   // low = a
    return *reinterpret_cast<uint32_t*>(&h);
}

// Permutation for 16 warps x 2 mtiles: warp w, mtile mt, mma row (g | g+8) ->
// gate (2*mt + s) of element e = w*8 + g, i.e. gate row R = (2*mt+s)*128 + e.
// Thread (w,lane) accumulators: dA = {i,f} x cols {c0,c0+1}, dB = {g,o} x cols,
// all for element e -> LSTM cell fully in registers, 2 states/thread.
__global__ void prep_Wfrag(const float* __restrict__ Wih,
                           const float* __restrict__ Whh,
                           uint4* __restrict__ w_out) {
    int idx = blockIdx.x * blockDim.x + threadIdx.x;
    if (idx >= NFRAG) return;
    int frag = idx >> 5, lane = idx & 31;
    int w = frag / FPW, rem = frag - w * FPW;
    int mt = rem / NKT, kt = rem - mt * NKT;
    int g = lane >> 2, t4 = lane & 3;
    int e = w * 8 + g;
    int R0 = (2 * mt + 0) * 128 + e;   // s=0 (mma row g)
    int R1 = (2 * mt + 1) * 128 + e;   // s=1 (mma row g+8)
    int kc = kt * 16 + 2 * t4;
    float v[8];
    v[0] = getW(Wih, Whh, R0, kc);     v[1] = getW(Wih, Whh, R0, kc + 1);
    v[2] = getW(Wih, Whh, R1, kc);     v[3] = getW(Wih, Whh, R1, kc + 1);
    v[4] = getW(Wih, Whh, R0, kc + 8); v[5] = getW(Wih, Whh, R0, kc + 9);
    v[6] = getW(Wih, Whh, R1, kc + 8); v[7] = getW(Wih, Whh, R1, kc + 9);
    w_out[idx] = make_uint4(packh2(v[0], v[1]), packh2(v[2], v[3]),
                            packh2(v[4], v[5]), packh2(v[6], v[7]));
}

__global__ void prep_fe(const int* __restrict__ cat, const float* __restrict__ cont,
                        const float* __restrict__ X, const float* __restrict__ emb,
                        const float* __restrict__ cw, float* __restrict__ out) {
    size_t idx = (size_t)blockIdx.x * blockDim.x + threadIdx.x;
    if (idx >= (size_t)BB * LL * EINF) return;
    size_t bl = idx / EINF;
    int j = (int)(idx - bl * EINF);
    float v;
    if (j < 16)       v = emb[cat[bl] * 16 + j];
    else if (j == 16) v = cont[bl] * cw[0];
    else              v = X[bl];
    out[idx] = v;
}

__global__ void prep_fd(const int* __restrict__ cat, const float* __restrict__ cont,
                        const float* __restrict__ emb, const float* __restrict__ cw,
                        float* __restrict__ out) {
    int idx = blockIdx.x * blockDim.x + threadIdx.x;
    if (idx >= BB * DEC * 17) return;
    int bl = idx / 17, j = idx - bl * 17;
    out[idx] = (j < 16) ? emb[cat[bl] * 16 + j] : cont[bl] * cw[0];
}

// ---------------- main persistent kernel ----------------
__global__ void __launch_bounds__(NTHR, 1)
model_kernel(const float* __restrict__ b_e, const float* __restrict__ b_d,
             const float* __restrict__ Wm, const float* __restrict__ bm,
             const float* __restrict__ Wsw, const float* __restrict__ bs,
             const float* __restrict__ Wv, const float* __restrict__ bv,
             float* __restrict__ out) {
    extern __shared__ char smem[];
    __half* xbuf[2] = { reinterpret_cast<__half*>(smem + XH0_OFF),
                        reinterpret_cast<__half*>(smem + XH1_OFF) };
    float*  hbuf = reinterpret_cast<float*>(smem + HBUF_OFF);
    float*  hw   = reinterpret_cast<float*>(smem + HW_OFF);

    const int tid = threadIdx.x;
    const int b0r = blockIdx.x * BT;
    const int w = tid >> 5, lane = tid & 31;
    const int g = lane >> 2, t4 = lane & 3;
    const int e  = w * 8 + g;             // this thread's cell element
    const int c0 = 2 * t4;                // this thread's 2 batch cols: c0, c0+1

    // ---- load encoder W into registers (20 frags = 80 regs) ----
    uint4 Wh[FPW];
    {
        const uint4* src = g_Whf_e + (size_t)w * FPW * 32 + lane;
#pragma unroll
        for (int i = 0; i < FPW; ++i) Wh[i] = src[i * 32];
    }
    // biases for element e
    float bi = b_e[e], bf = b_e[128 + e], bg = b_e[256 + e], bo = b_e[384 + e];

    // zero both xh buffers (h0 = 0; K padding stays 0 forever)
    for (int i = tid; i < (2 * BT * XST) / 2; i += NTHR)
        reinterpret_cast<uint32_t*>(xbuf[0])[i] = 0;

    // head weights
    if (tid < 128) {
        hw[tid]       = Wm[tid];
        hw[128 + tid] = Wsw[tid];
#pragma unroll
        for (int d = 0; d < 4; ++d) hw[256 + d * 128 + tid] = Wv[d * 128 + tid];
    }
    if (tid == 0) {
        hw[768] = bm[0]; hw[769] = bs[0];
        hw[770] = bv[0]; hw[771] = bv[1]; hw[772] = bv[2]; hw[773] = bv[3];
    }
    __syncthreads();
    // initial x features (t=0) -> buffer 0
    if (tid < BT * EINF) {
        int pr = tid / EINF, pk = tid - pr * EINF;
        xbuf[0][pr * XST + pk] =
            __float2half(g_fe[(size_t)(b0r + pr) * (LL * EINF) + pk]);
    }

    float c[2] = {0.f, 0.f};   // states: (e,c0), (e,c0+1)

#pragma unroll 1
    for (int t = 0; t < LL + DEC; ++t) {
        if (t == LL) {
            const uint4* src = g_Whf_d + (size_t)w * FPW * 32 + lane;
#pragma unroll
            for (int i = 0; i < FPW; ++i) Wh[i] = src[i * 32];
            bi = b_d[e]; bf = b_d[128 + e]; bg = b_d[256 + e]; bo = b_d[384 + e];
        }
        const __half* cur = xbuf[t & 1];
        __half*       nxt = xbuf[(t + 1) & 1];
        __syncthreads();                      // cur complete (h + features)

        // ---- ISSUE feature prefetch LDG early; MMA phase hides its latency ----
        float pf = 0.0f; bool havepf = false; int pr = 0, pk = 0;
        if (t < LL - 1) {
            if (tid < BT * EINF) {
                havepf = true; pr = tid / EINF; pk = tid - pr * EINF;
                pf = g_fe[(size_t)(b0r + pr) * (LL * EINF) + (size_t)(t + 1) * EINF + pk];
            }
        } else if (t >= LL && t < LL + DEC - 1) {
            int td = t - LL;
            if (tid < BT * 17) {
                havepf = true; pr = tid / 17; pk = tid - pr * 17;
                pf = g_fd[((b0r + pr) * DEC + td) * 17 + pk];
            }
        }

        // ---- gate GEMM: B-frags loaded per k-tile (low reg pressure) ----
        const __half* xp = cur + g * XST;
        float dA[4], dB[4];                   // dA = {i,f}, dB = {g,o}
        dA[0] = bi; dA[1] = bi; dA[2] = bf; dA[3] = bf;
        dB[0] = bg; dB[1] = bg; dB[2] = bo; dB[3] = bo;
#pragma unroll
        for (int kt = 0; kt < NKT; ++kt) {
            uint32_t b0 = *reinterpret_cast<const uint32_t*>(xp + kt * 16 + 2 * t4);
            uint32_t b1 = *reinterpret_cast<const uint32_t*>(xp + kt * 16 + 2 * t4 + 8);
            mma_f16(dA, Wh[kt],       b0, b1);
            mma_f16(dB, Wh[NKT + kt], b0, b1);
        }

        // ---- LSTM cell: fully in registers (2 states/thread) ----
        c[0] = sg(dA[2]) * c[0] + sg(dA[0]) * th(dB[0]);
        c[1] = sg(dA[3]) * c[1] + sg(dA[1]) * th(dB[1]);
        float h0 = sg(dB[2]) * th(c[0]);
        float h1 = sg(dB[3]) * th(c[1]);
        nxt[c0 * XST + 18 + e]       = __float2half(h0);
        nxt[(c0 + 1) * XST + 18 + e] = __float2half(h1);

        // ---- store prefetched features / seam copy ----
        if (havepf) {
            nxt[pr * XST + pk] = __float2half(pf);
        } else if (t == LL - 1) {
            // decoder t0 reuses encoder's last features (f_prev, x_prev)
            if (tid < BT * EINF) {
                int qr = tid / EINF, qk = tid - qr * EINF;
                nxt[qr * XST + qk] = cur[qr * XST + qk];
            }
        }

        // ---- decoder heads ----
        if (t >= LL) {
            int td = t - LL;
            *reinterpret_cast<float2*>(hbuf + e * BT + c0) = make_float2(h0, h1);
            __syncthreads();                  // h complete for heads
            if (w < 8) {
                int r = w;                    // warps 0-7 -> 8 batch rows
                float hm = 0.f, hs = 0.f, hv0 = 0.f, hv1 = 0.f, hv2 = 0.f, hv3 = 0.f;
#pragma unroll
                for (int q4 = 0; q4 < 4; ++q4) {
                    int jj = lane + q4 * 32;
                    float hh = hbuf[jj * BT + r];
                    hm  = fmaf(hh, hw[jj], hm);
                    hs  = fmaf(hh, hw[128 + jj], hs);
                    hv0 = fmaf(hh, hw[256 + jj], hv0);
                    hv1 = fmaf(hh, hw[384 + jj], hv1);
                    hv2 = fmaf(hh, hw[512 + jj], hv2);
                    hv3 = fmaf(hh, hw[640 + jj], hv3);
                }
#pragma unroll
                for (int off = 16; off; off >>= 1) {
                    hm  += __shfl_xor_sync(0xffffffffu, hm,  off);
                    hs  += __shfl_xor_sync(0xffffffffu, hs,  off);
                    hv0 += __shfl_xor_sync(0xffffffffu, hv0, off);
                    hv1 += __shfl_xor_sync(0xffffffffu, hv1, off);
                    hv2 += __shfl_xor_sync(0xffffffffu, hv2, off);
                    hv3 += __shfl_xor_sync(0xffffffffu, hv3, off);
                }
                if (lane == 0) {
                    float mu = hm + hw[768];
                    float sp = hs + hw[769];
                    float stdv = fmaxf(sp, 0.0f) + log1pf(__expf(-fabsf(sp)));
                    int b = b0r + r;
                    out[b * DEC + td] = mu;
                    out[BB * DEC + b * DEC + td] = stdv;
                    float* vo = out + 2 * BB * DEC + (b * DEC + td) * 4;
                    vo[0] = hv0 + hw[770]; vo[1] = hv1 + hw[771];
                    vo[2] = hv2 + hw[772]; vo[3] = hv3 + hw[773];
                    nxt[r * XST + 17] = __float2half(mu);   // mu feedback -> x_prev
                }
            }
        }
    }
}

// ---------------- launch ----------------
extern "C" void kernel_launch(void* const* d_in, const int* in_sizes, int n_in,
                              void* d_out, int out_size) {
    const int*   cat_in   = (const int*)d_in[0];
    const float* cont_in  = (const float*)d_in[1];
    const float* X_in     = (const float*)d_in[2];
    const int*   cat_out  = (const int*)d_in[3];
    const float* cont_out = (const float*)d_in[4];
    const float* emb      = (const float*)d_in[5];
    const float* cw       = (const float*)d_in[6];
    const float* Wih_e    = (const float*)d_in[7];
    const float* Whh_e    = (const float*)d_in[8];
    const float* b_e      = (const float*)d_in[9];
    const float* Wih_d    = (const float*)d_in[10];
    const float* Whh_d    = (const float*)d_in[11];
    const float* b_d      = (const float*)d_in[12];
    const float* Wm       = (const float*)d_in[13];
    const float* bm       = (const float*)d_in[14];
    const float* Ws       = (const float*)d_in[15];
    const float* bs       = (const float*)d_in[16];
    const float* Wv       = (const float*)d_in[17];
    const float* bv       = (const float*)d_in[18];
    float* out = (float*)d_out;

    uint4 *pWhe, *pWhd;
    float *pfe, *pfd;
    cudaGetSymbolAddress((void**)&pWhe, g_Whf_e);
    cudaGetSymbolAddress((void**)&pWhd, g_Whf_d);
    cudaGetSymbolAddress((void**)&pfe,  g_fe);
    cudaGetSymbolAddress((void**)&pfd,  g_fd);

    prep_Wfrag<<<(NFRAG + 255) / 256, 256>>>(Wih_e, Whh_e, pWhe);
    prep_Wfrag<<<(NFRAG + 255) / 256, 256>>>(Wih_d, Whh_d, pWhd);
    size_t ne = (size_t)BB * LL * EINF;
    prep_fe<<<(unsigned)((ne + 255) / 256), 256>>>(cat_in, cont_in, X_in, emb, cw, pfe);
    prep_fd<<<(BB * DEC * 17 + 255) / 256, 256>>>(cat_out, cont_out, emb, cw, pfd);

    cudaFuncSetAttribute(model_kernel, cudaFuncAttributeMaxDynamicSharedMemorySize,
                         SMEM_TOTAL);
    model_kernel<<<NCTA, NTHR, SMEM_TOTAL>>>(b_e, b_d, Wm, bm, Ws, bs, Wv, bv, out);
}